// round 1
// baseline (speedup 1.0000x reference)
#include <cuda_runtime.h>
#include <cstdint>
#include <cstddef>

// Problem constants
#define TM      128     // rows per CTA
#define KC      32      // k-chunk
#define NT      256     // threads per CTA
#define LATENT  256
#define NNODES  256
#define NROWS   65536
#define ZS_STRIDE 130   // padded (even -> 8B-aligned u64 reads)
#define ES_STRIDE 260   // padded (mult of 4 -> 16B-aligned float4 reads)
#define EPSF    1.1920929e-7f

typedef unsigned long long u64;

// Packed 2-wide fp32 FMA (FFMA2) — PTX-only on sm_103a, 2x FFMA throughput.
__device__ __forceinline__ u64 ffma2(u64 a, u64 b, u64 c) {
    u64 d;
    asm("fma.rn.f32x2 %0, %1, %2, %3;" : "=l"(d) : "l"(a), "l"(b), "l"(c));
    return d;
}
__device__ __forceinline__ u64 pack2(float x) {
    u64 d;
    asm("mov.b64 %0, {%1, %1};" : "=l"(d) : "f"(x));
    return d;
}

extern __shared__ float smf[];

__global__ void __launch_bounds__(NT, 1)
som_kernel(const float* __restrict__ Z, const float* __restrict__ E,
           const int* __restrict__ Alpha, float* __restrict__ out)
{
    // ---- shared layout (floats) ----
    float* zs   = smf;                        // KC*ZS_STRIDE = 4160
    float* es   = zs + KC * ZS_STRIDE;        // KC*ES_STRIDE = 8320
    float* e2   = es + KC * ES_STRIDE;        // 256
    float* z2   = e2 + NNODES;                // 128
    float* redv = z2 + TM;                    // 128*32
    float* reds = redv + TM * 32;             // 128*32
    int*   redi = (int*)(reds + TM * 32);     // 128*32
    int*   bmuS = redi + TM * 32;             // 128
    float* rqs  = (float*)(bmuS + TM);        // 128

    const int t  = threadIdx.x;
    const int R0 = blockIdx.x * TM;
    const int cg = t & 31;          // node-column group (8 nodes)
    const int rg = t >> 5;          // row group (16 rows)
    const int c0 = cg * 8;
    const int r0 = rg * 16;

    // ---- e2[j] = ||e_j||^2 (one node per thread), z2[r] for this tile ----
    {
        const float4* er = (const float4*)(E + (size_t)t * LATENT);
        float s = 0.f;
        #pragma unroll 8
        for (int i = 0; i < 64; i++) { float4 v = er[i]; s += v.x*v.x + v.y*v.y + v.z*v.z + v.w*v.w; }
        e2[t] = s;
    }
    if (t < TM) {
        const float4* zr = (const float4*)(Z + (size_t)(R0 + t) * LATENT);
        float s = 0.f;
        #pragma unroll 8
        for (int i = 0; i < 64; i++) { float4 v = zr[i]; s += v.x*v.x + v.y*v.y + v.z*v.z + v.w*v.w; }
        z2[t] = s;
    }

    // ---- GEMM: dot[r][j], per-thread 16 rows (8 f32x2 pairs) x 8 nodes ----
    u64 acc[8][8];
    #pragma unroll
    for (int p = 0; p < 8; p++)
        #pragma unroll
        for (int n = 0; n < 8; n++) acc[p][n] = 0ull;

    for (int c = 0; c < LATENT; c += KC) {
        __syncthreads();   // previous chunk's compute done before smem overwrite
        // z tile: 128 rows x KC, stored transposed zs[k][row]
        #pragma unroll
        for (int i = 0; i < 4; i++) {
            int v = t + NT * i;
            int row = v >> 3, kq = v & 7;
            float4 zv = *(const float4*)(Z + (size_t)(R0 + row) * LATENT + c + kq * 4);
            float* p0 = zs + (kq * 4) * ZS_STRIDE + row;
            p0[0]             = zv.x;
            p0[ZS_STRIDE]     = zv.y;
            p0[2 * ZS_STRIDE] = zv.z;
            p0[3 * ZS_STRIDE] = zv.w;
        }
        // e tile: thread t loads node t's KC slice, stored transposed es[k][node]
        {
            const float4* er = (const float4*)(E + (size_t)t * LATENT + c);
            #pragma unroll
            for (int j = 0; j < 8; j++) {
                float4 ev = er[j];
                float* p0 = es + (j * 4) * ES_STRIDE + t;
                p0[0]             = ev.x;
                p0[ES_STRIDE]     = ev.y;
                p0[2 * ES_STRIDE] = ev.z;
                p0[3 * ES_STRIDE] = ev.w;
            }
        }
        __syncthreads();
        #pragma unroll 2
        for (int k = 0; k < KC; k++) {
            const u64* zp = (const u64*)(zs + k * ZS_STRIDE + r0);
            u64 zf[8];
            #pragma unroll
            for (int p2 = 0; p2 < 8; p2++) zf[p2] = zp[p2];
            const float* ep = es + k * ES_STRIDE + c0;
            u64 ef[8];
            #pragma unroll
            for (int n = 0; n < 8; n++) ef[n] = pack2(ep[n]);
            #pragma unroll
            for (int n = 0; n < 8; n++)
                #pragma unroll
                for (int p2 = 0; p2 < 8; p2++)
                    acc[p2][n] = ffma2(zf[p2], ef[n], acc[p2][n]);
        }
    }
    __syncthreads();

    // ---- alpha (robust to int32/int64-low-word/float32 encodings) ----
    int ai = Alpha[0];
    float a = (ai > 0 && ai < 1000000) ? (float)ai : __int_as_float(ai);
    float inva = 1.0f / a;
    float coef = -(a + 1.0f) * 0.5f;

    // ---- per-(row, node) d, q; per-row local argmin (first-index ties) + qsum ----
    float rmin[16], rsum[16];
    int   rid[16];
    #pragma unroll
    for (int i = 0; i < 16; i++) { rmin[i] = 3.4e38f; rsum[i] = 0.f; rid[i] = 0; }

    #pragma unroll
    for (int p = 0; p < 8; p++) {
        float z2l = z2[r0 + 2 * p], z2h = z2[r0 + 2 * p + 1];
        #pragma unroll
        for (int n = 0; n < 8; n++) {
            int j = c0 + n;
            float e2j = e2[j];
            u64 av = acc[p][n];
            float dotl = __uint_as_float((unsigned)av);
            float doth = __uint_as_float((unsigned)(av >> 32));
            float dl = fmaxf(z2l + e2j - 2.f * dotl, 0.f);
            float dh = fmaxf(z2h + e2j - 2.f * doth, 0.f);
            float ql = exp2f(coef * __log2f(fmaf(dl, inva, 1.0f)));
            float qh = exp2f(coef * __log2f(fmaf(dh, inva, 1.0f)));
            if (dl < rmin[2 * p])     { rmin[2 * p]     = dl; rid[2 * p]     = j; }
            if (dh < rmin[2 * p + 1]) { rmin[2 * p + 1] = dh; rid[2 * p + 1] = j; }
            rsum[2 * p]     += ql;
            rsum[2 * p + 1] += qh;
            // reuse accumulator registers to hold raw q (lo,hi packed)
            acc[p][n] = ((u64)__float_as_uint(qh) << 32) | (u64)__float_as_uint(ql);
        }
    }
    #pragma unroll
    for (int i = 0; i < 16; i++) {
        int row = r0 + i;
        redv[row * 32 + cg] = rmin[i];
        redi[row * 32 + cg] = rid[i];
        reds[row * 32 + cg] = rsum[i];
    }
    __syncthreads();

    // ---- cross-column reduction: bmu + 1/qsum per row ----
    if (t < TM) {
        float bv = 3.4e38f; int bi = 0; float s = 0.f;
        #pragma unroll 4
        for (int g = 0; g < 32; g++) {
            float v = redv[t * 32 + g];
            s += reds[t * 32 + g];
            if (v < bv) { bv = v; bi = redi[t * 32 + g]; }   // strict < keeps lowest index
        }
        bmuS[t] = bi;
        rqs[t]  = 1.0f / s;
    }
    __syncthreads();

    // ---- output layout (floats): [z_q | z_q_neighbors | q | bmu] ----
    const size_t NBOFF  = (size_t)NROWS * 256;
    const size_t QOFF   = (size_t)NROWS * 1536;
    const size_t BMUOFF = (size_t)NROWS * 1792;

    // q = qraw/sum + eps
    #pragma unroll
    for (int p = 0; p < 8; p++) {
        #pragma unroll
        for (int h = 0; h < 2; h++) {
            int row = r0 + 2 * p + h;
            float rq = rqs[row];
            float v[8];
            #pragma unroll
            for (int n = 0; n < 8; n++) {
                u64 av = acc[p][n];
                unsigned bits = h ? (unsigned)(av >> 32) : (unsigned)av;
                v[n] = fmaf(__uint_as_float(bits), rq, EPSF);
            }
            float4* dst = (float4*)(out + QOFF + (size_t)(R0 + row) * NNODES + c0);
            dst[0] = make_float4(v[0], v[1], v[2], v[3]);
            dst[1] = make_float4(v[4], v[5], v[6], v[7]);
        }
    }

    // bmu (as float value)
    if (t < TM) out[BMUOFF + R0 + t] = (float)bmuS[t];

    // z_q + neighbor gathers: 6 row-copies per row, one warp per copy
    const int lane = t & 31, wid = t >> 5;
    for (int cp = wid; cp < TM * 6; cp += 8) {
        int row = cp / 6;
        int s   = cp - row * 6;
        int b   = bmuS[row];
        int idx;
        if (s <= 1) {
            idx = b;                                    // z_q, neighbors[0]=self
        } else {
            int k1 = b >> 4, k2 = b & 15;
            if      (s == 2) idx = (((k1 + 15) & 15) << 4) + k2;   // up
            else if (s == 3) idx = (((k1 + 1)  & 15) << 4) + k2;   // down
            else if (s == 4) idx = (k1 << 4) + ((k2 + 1)  & 15);   // right
            else             idx = (k1 << 4) + ((k2 + 15) & 15);   // left
        }
        const float4* src = (const float4*)(E + (size_t)idx * LATENT);
        float4 a0 = src[lane], a1 = src[lane + 32];
        float* dstp = (s == 0)
            ? out + (size_t)(R0 + row) * LATENT
            : out + NBOFF + ((size_t)(R0 + row) * 5 + (s - 1)) * LATENT;
        float4* d4 = (float4*)dstp;
        d4[lane]      = a0;
        d4[lane + 32] = a1;
    }
}

// Shared memory bytes
#define SMEM_FLOATS (KC*ZS_STRIDE + KC*ES_STRIDE + NNODES + TM + 3*TM*32 + TM + TM)
#define SMEM_BYTES  (SMEM_FLOATS * 4)

extern "C" void kernel_launch(void* const* d_in, const int* in_sizes, int n_in,
                              void* d_out, int out_size) {
    const float* Z = (const float*)d_in[0];
    const float* E = (const float*)d_in[1];
    const int*   A = (const int*)d_in[2];
    float* out = (float*)d_out;

    cudaFuncSetAttribute(som_kernel, cudaFuncAttributeMaxDynamicSharedMemorySize, SMEM_BYTES);
    som_kernel<<<NROWS / TM, NT, SMEM_BYTES>>>(Z, E, A, out);
}